// round 8
// baseline (speedup 1.0000x reference)
#include <cuda_runtime.h>
#include <cuda_bf16.h>

#define B_IMGS 64
#define CH 3
#define H_MAX 512
#define W_STRIDE 513            // stored width is W_max+1
#define OUT_H 224
#define OUT_W 224

__global__ __launch_bounds__(OUT_W) void center_crop3_kernel(
    const float* __restrict__ x, float* __restrict__ out)
{
    const int b   = blockIdx.y;            // 0..63
    const int oy0 = blockIdx.x * 2;        // 0,2,..,222 (pair of rows)
    const int ox  = threadIdx.x;           // 0..223

    const float* img = x + (size_t)b * CH * H_MAX * W_STRIDE;

    // h at x[b,0,0,W_max], w at x[b,1,0,W_max]  (broadcast loads)
    const float h = __ldg(img + (W_STRIDE - 1));
    const float w = __ldg(img + (size_t)H_MAX * W_STRIDE + (W_STRIDE - 1));

    // ---- discrete part: bit-exact vs XLA ----
    const float min_dim = fminf(h, w);
    const float scale   = __fdiv_rn(256.0f, min_dim);   // IEEE rn
    const float h_res   = rintf(h * scale);             // half-to-even = jnp.round
    const float w_res   = rintf(w * scale);
    const float top     = rintf((h_res - (float)OUT_H) * 0.5f);
    const float left    = rintf((w_res - (float)OUT_W) * 0.5f);

    // ---- continuous part: approx div OK (bilinear continuous in src coords) ----
    float sx = __fdividef((((float)ox + left) + 0.5f) * w, w_res) - 0.5f;
    sx = fminf(fmaxf(sx, 0.0f), w - 1.0f);
    const float x0f = floorf(sx);
    const float wxv = sx - x0f;
    const int wi = (int)w - 1;
    int x0 = min(max((int)x0f, 0), wi);
    const int x1 = min(x0 + 1, wi);

    const int hi = (int)h - 1;
    int   ya0[2], ya1[2];
    float wyv[2];
#pragma unroll
    for (int r = 0; r < 2; r++) {
        float sy = __fdividef((((float)(oy0 + r) + top) + 0.5f) * h, h_res) - 0.5f;
        sy = fminf(fmaxf(sy, 0.0f), h - 1.0f);
        const float y0f = floorf(sy);
        wyv[r] = sy - y0f;
        int y0 = min(max((int)y0f, 0), hi);
        const int y1 = min(y0 + 1, hi);
        ya0[r] = y0 * W_STRIDE;
        ya1[r] = y1 * W_STRIDE;
    }

    // ---- issue ALL 24 gathers up front (one long-scoreboard wait, MLP=24) ----
    float v[CH][8];
#pragma unroll
    for (int c = 0; c < CH; c++) {
        const float* p = img + (size_t)c * (H_MAX * W_STRIDE);
        v[c][0] = __ldg(p + ya0[0] + x0);
        v[c][1] = __ldg(p + ya0[0] + x1);
        v[c][2] = __ldg(p + ya1[0] + x0);
        v[c][3] = __ldg(p + ya1[0] + x1);
        v[c][4] = __ldg(p + ya0[1] + x0);
        v[c][5] = __ldg(p + ya0[1] + x1);
        v[c][6] = __ldg(p + ya1[1] + x0);
        v[c][7] = __ldg(p + ya1[1] + x1);
    }

    float* o = out + (((size_t)b * CH) * OUT_H + oy0) * OUT_W + ox;

#pragma unroll
    for (int c = 0; c < CH; c++) {
        {
            const float top_v = v[c][0] + (v[c][1] - v[c][0]) * wxv;
            const float bot_v = v[c][2] + (v[c][3] - v[c][2]) * wxv;
            o[(size_t)c * (OUT_H * OUT_W)] = top_v + (bot_v - top_v) * wyv[0];
        }
        {
            const float top_v = v[c][4] + (v[c][5] - v[c][4]) * wxv;
            const float bot_v = v[c][6] + (v[c][7] - v[c][6]) * wxv;
            o[(size_t)c * (OUT_H * OUT_W) + OUT_W] = top_v + (bot_v - top_v) * wyv[1];
        }
    }
}

extern "C" void kernel_launch(void* const* d_in, const int* in_sizes, int n_in,
                              void* d_out, int out_size)
{
    const float* x = (const float*)d_in[0];
    float* out = (float*)d_out;
    dim3 grid(OUT_H / 2, B_IMGS);
    center_crop3_kernel<<<grid, OUT_W>>>(x, out);
}

// round 10
// speedup vs baseline: 1.0013x; 1.0013x over previous
#include <cuda_runtime.h>
#include <cuda_bf16.h>

#define B_IMGS 64
#define CH 3
#define H_MAX 512
#define W_STRIDE 513            // stored width is W_max+1
#define OUT_H 224
#define OUT_W 224
#define ROWS_PER_BLK 4

__global__ __launch_bounds__(OUT_W, 1) void center_crop4_kernel(
    const float* __restrict__ x, float* __restrict__ out)
{
    const int b   = blockIdx.y;                    // 0..63
    const int oy0 = blockIdx.x * ROWS_PER_BLK;     // 0,4,..,220
    const int ox  = threadIdx.x;                   // 0..223

    const float* img = x + (size_t)b * CH * H_MAX * W_STRIDE;

    // h at x[b,0,0,W_max], w at x[b,1,0,W_max]  (broadcast loads)
    const float h = __ldg(img + (W_STRIDE - 1));
    const float w = __ldg(img + (size_t)H_MAX * W_STRIDE + (W_STRIDE - 1));

    // ---- discrete part: bit-exact vs XLA ----
    const float min_dim = fminf(h, w);
    const float scale   = __fdiv_rn(256.0f, min_dim);   // IEEE rn
    const float h_res   = rintf(h * scale);             // half-to-even = jnp.round
    const float w_res   = rintf(w * scale);
    const float top     = rintf((h_res - (float)OUT_H) * 0.5f);
    const float left    = rintf((w_res - (float)OUT_W) * 0.5f);

    // ---- continuous part: approx div OK (bilinear continuous in src coords) ----
    float sx = __fdividef((((float)ox + left) + 0.5f) * w, w_res) - 0.5f;
    sx = fminf(fmaxf(sx, 0.0f), w - 1.0f);
    const float x0f = floorf(sx);
    const float wxv = sx - x0f;
    const int wi = (int)w - 1;
    int x0 = min(max((int)x0f, 0), wi);
    const int x1 = min(x0 + 1, wi);

    const int hi = (int)h - 1;
    int   ya0[ROWS_PER_BLK], ya1[ROWS_PER_BLK];
    float wyv[ROWS_PER_BLK];
#pragma unroll
    for (int r = 0; r < ROWS_PER_BLK; r++) {
        float sy = __fdividef((((float)(oy0 + r) + top) + 0.5f) * h, h_res) - 0.5f;
        sy = fminf(fmaxf(sy, 0.0f), h - 1.0f);
        const float y0f = floorf(sy);
        wyv[r] = sy - y0f;
        int y0 = min(max((int)y0f, 0), hi);
        const int y1 = min(y0 + 1, hi);
        ya0[r] = y0 * W_STRIDE;
        ya1[r] = y1 * W_STRIDE;
    }

    // ---- 48 independent gathers; __launch_bounds__(224,1) frees the register
    //      budget so ptxas can keep them in flight ----
    float v[CH][ROWS_PER_BLK * 4];
#pragma unroll
    for (int c = 0; c < CH; c++) {
        const float* p = img + (size_t)c * (H_MAX * W_STRIDE);
#pragma unroll
        for (int r = 0; r < ROWS_PER_BLK; r++) {
            v[c][r * 4 + 0] = __ldg(p + ya0[r] + x0);
            v[c][r * 4 + 1] = __ldg(p + ya0[r] + x1);
            v[c][r * 4 + 2] = __ldg(p + ya1[r] + x0);
            v[c][r * 4 + 3] = __ldg(p + ya1[r] + x1);
        }
    }

    float* o = out + (((size_t)b * CH) * OUT_H + oy0) * OUT_W + ox;

#pragma unroll
    for (int c = 0; c < CH; c++) {
#pragma unroll
        for (int r = 0; r < ROWS_PER_BLK; r++) {
            const float top_v = v[c][r * 4 + 0] + (v[c][r * 4 + 1] - v[c][r * 4 + 0]) * wxv;
            const float bot_v = v[c][r * 4 + 2] + (v[c][r * 4 + 3] - v[c][r * 4 + 2]) * wxv;
            o[(size_t)c * (OUT_H * OUT_W) + (size_t)r * OUT_W] =
                top_v + (bot_v - top_v) * wyv[r];
        }
    }
}

extern "C" void kernel_launch(void* const* d_in, const int* in_sizes, int n_in,
                              void* d_out, int out_size)
{
    const float* x = (const float*)d_in[0];
    float* out = (float*)d_out;
    dim3 grid(OUT_H / ROWS_PER_BLK, B_IMGS);
    center_crop4_kernel<<<grid, OUT_W>>>(x, out);
}